// round 1
// baseline (speedup 1.0000x reference)
#include <cuda_runtime.h>

#define B_   256
#define H_   6
#define NT   343
#define DH   32
#define C_   192
#define NWIN 32
#define M_   (B_*NT)          // 87808
#define KSTR 36               // padded smem row stride (floats)

// Scratch (static device allocations — allowed)
__device__ __align__(16) float g_k[(size_t)B_*H_*NT*DH];
__device__ __align__(16) float g_v[(size_t)B_*H_*NT*DH];
__device__ __align__(16) float g_x[(size_t)B_*NT*C_];
__device__ __align__(16) float g_bias[(size_t)H_*NT*NT];

// ---------------------------------------------------------------------------
// Kernel 1: gather relative-position bias  bias[h][i][j] = table[rel[i][j]][h]
// ---------------------------------------------------------------------------
__global__ void bias_gather_kernel(const int* __restrict__ rel,
                                   const float* __restrict__ table,
                                   float* __restrict__ bias) {
    int idx = blockIdx.x * 256 + threadIdx.x;
    if (idx < NT * NT) {
        int r = rel[idx];
        #pragma unroll
        for (int h = 0; h < H_; h++)
            bias[(size_t)h * (NT * NT) + idx] = table[r * H_ + h];
    }
}

// ---------------------------------------------------------------------------
// Tiled fp32 GEMM: (M x 192) @ (192 x NCOL) + bias, 64x64 tiles, 256 threads,
// 4x4 per thread. MODE 0: scatter kv -> g_k/g_v ; MODE 1: row-major out.
// M=87808, NCOL in {384,192}: all dims divide tiles exactly, no bounds checks.
// ---------------------------------------------------------------------------
template <int NCOL, int MODE>
__global__ void gemm_kernel(const float* __restrict__ A,
                            const float* __restrict__ W,
                            const float* __restrict__ bias,
                            float* __restrict__ out0,
                            float* __restrict__ out1) {
    __shared__ float As[16][64];
    __shared__ float Bs[16][68];

    const int t  = threadIdx.x;          // 0..255
    const int M0 = blockIdx.x * 64;
    const int N0 = blockIdx.y * 64;
    const int ty = t >> 4, tx = t & 15;
    const int ar = t >> 2, ac = (t & 3) << 2;
    const int br = t >> 4, bc = (t & 15) << 2;

    float c[4][4] = {};

    for (int k0 = 0; k0 < 192; k0 += 16) {
        float4 a4 = *(const float4*)&A[(size_t)(M0 + ar) * 192 + k0 + ac];
        As[ac + 0][ar] = a4.x;
        As[ac + 1][ar] = a4.y;
        As[ac + 2][ar] = a4.z;
        As[ac + 3][ar] = a4.w;
        float4 b4 = *(const float4*)&W[(size_t)(k0 + br) * NCOL + N0 + bc];
        *(float4*)&Bs[br][bc] = b4;
        __syncthreads();
        #pragma unroll
        for (int kk = 0; kk < 16; kk++) {
            float4 av = *(const float4*)&As[kk][ty << 2];
            float4 bv = *(const float4*)&Bs[kk][tx << 2];
            float aa[4] = {av.x, av.y, av.z, av.w};
            float bb[4] = {bv.x, bv.y, bv.z, bv.w};
            #pragma unroll
            for (int i = 0; i < 4; i++)
                #pragma unroll
                for (int j = 0; j < 4; j++)
                    c[i][j] += aa[i] * bb[j];
        }
        __syncthreads();
    }

    #pragma unroll
    for (int i = 0; i < 4; i++) {
        int row = M0 + (ty << 2) + i;
        int b = row / NT, nn = row - b * NT;
        #pragma unroll
        for (int j = 0; j < 4; j++) {
            int col = N0 + (tx << 2) + j;
            float val = c[i][j] + bias[col];
            if (MODE == 0) {
                int p   = col / 192;
                int rem = col - p * 192;
                int h   = rem >> 5;
                int d   = rem & 31;
                float* dst = p ? out1 : out0;
                dst[((size_t)(b * H_ + h) * NT + nn) * DH + d] = val;
            } else {
                out0[(size_t)row * NCOL + col] = val;
            }
        }
    }
}

// ---------------------------------------------------------------------------
// Kernel 3: fused window attention. One CTA per (b,h). 256 threads = 8 warps.
// k,v staged in smem (row stride 36 floats -> conflict-free). Warp per row:
// scores (float4 dots) + bias + mask, shuffle softmax, p->smem, AV lane=d.
// ---------------------------------------------------------------------------
__global__ void attn_kernel(const float* __restrict__ xup,
                            const float* __restrict__ gk,
                            const float* __restrict__ gv,
                            const float* __restrict__ bias,
                            const float* __restrict__ mask,
                            float* __restrict__ xout) {
    extern __shared__ float sm[];
    float* ks = sm;                       // 344*36
    float* vs = sm + 344 * KSTR;          // 344*36 (row 343 zeroed)
    float* ps = sm + 2 * 344 * KSTR;      // 8 * 344

    const int tid = threadIdx.x;
    const int bh  = blockIdx.x;           // b*6 + h
    const int b   = bh / H_;
    const int h   = bh - b * H_;
    const int w   = b & (NWIN - 1);

    const float4* kg = (const float4*)(gk + (size_t)bh * NT * DH);
    const float4* vg = (const float4*)(gv + (size_t)bh * NT * DH);

    for (int idx = tid; idx < NT * 8; idx += 256) {
        int j = idx >> 3, cc = idx & 7;
        float4 kv4 = kg[idx];
        *(float4*)&ks[j * KSTR + cc * 4] = kv4;
        float4 vv4 = vg[idx];
        *(float4*)&vs[j * KSTR + cc * 4] = vv4;
    }
    if (tid < KSTR) vs[343 * KSTR + tid] = 0.f;   // pad row for vectorized AV
    __syncthreads();

    const int warp = tid >> 5, lane = tid & 31;
    const float scale = 0.17677669529663687f;     // 32^-0.5
    float* pw = ps + warp * 344;
    const float* brow_base = bias + (size_t)h * NT * NT;
    const float* mrow_base = mask + (size_t)w * NT * NT;

    for (int i = warp; i < NT; i += 8) {
        // broadcast-load q row into registers (8 x float4)
        const float4* qg = (const float4*)(xup + ((size_t)b * NT + i) * C_ + h * DH);
        float4 q0 = qg[0], q1 = qg[1], q2 = qg[2], q3 = qg[3];
        float4 q4 = qg[4], q5 = qg[5], q6 = qg[6], q7 = qg[7];

        const float* brow = brow_base + (size_t)i * NT;
        const float* mrow = mrow_base + (size_t)i * NT;

        float sreg[11];
        #pragma unroll
        for (int tt = 0; tt < 11; tt++) {
            int j = lane + 32 * tt;
            float s = -1e30f;
            if (j < NT) {
                const float4* kr = (const float4*)&ks[j * KSTR];
                float4 k4;
                float acc;
                k4 = kr[0]; acc  = q0.x*k4.x + q0.y*k4.y + q0.z*k4.z + q0.w*k4.w;
                k4 = kr[1]; acc += q1.x*k4.x + q1.y*k4.y + q1.z*k4.z + q1.w*k4.w;
                k4 = kr[2]; acc += q2.x*k4.x + q2.y*k4.y + q2.z*k4.z + q2.w*k4.w;
                k4 = kr[3]; acc += q3.x*k4.x + q3.y*k4.y + q3.z*k4.z + q3.w*k4.w;
                k4 = kr[4]; acc += q4.x*k4.x + q4.y*k4.y + q4.z*k4.z + q4.w*k4.w;
                k4 = kr[5]; acc += q5.x*k4.x + q5.y*k4.y + q5.z*k4.z + q5.w*k4.w;
                k4 = kr[6]; acc += q6.x*k4.x + q6.y*k4.y + q6.z*k4.z + q6.w*k4.w;
                k4 = kr[7]; acc += q7.x*k4.x + q7.y*k4.y + q7.z*k4.z + q7.w*k4.w;
                s = acc * scale + brow[j] + mrow[j];
            }
            sreg[tt] = s;
        }

        // softmax (warp-wide)
        float mx = sreg[0];
        #pragma unroll
        for (int tt = 1; tt < 11; tt++) mx = fmaxf(mx, sreg[tt]);
        #pragma unroll
        for (int o = 16; o > 0; o >>= 1)
            mx = fmaxf(mx, __shfl_xor_sync(0xffffffffu, mx, o));
        float sum = 0.f;
        #pragma unroll
        for (int tt = 0; tt < 11; tt++) {
            float e = __expf(sreg[tt] - mx);
            sreg[tt] = e;
            sum += e;
        }
        #pragma unroll
        for (int o = 16; o > 0; o >>= 1)
            sum += __shfl_xor_sync(0xffffffffu, sum, o);
        float inv = 1.f / sum;
        #pragma unroll
        for (int tt = 0; tt < 11; tt++) {
            int j = lane + 32 * tt;
            if (j < NT) pw[j] = sreg[tt] * inv;
        }
        if (lane == 0) pw[343] = 0.f;
        __syncwarp();

        // AV: lane owns d = lane
        float out = 0.f;
        #pragma unroll 4
        for (int j4 = 0; j4 < 344; j4 += 4) {
            float4 p4 = *(const float4*)&pw[j4];
            out += p4.x * vs[(j4 + 0) * KSTR + lane];
            out += p4.y * vs[(j4 + 1) * KSTR + lane];
            out += p4.z * vs[(j4 + 2) * KSTR + lane];
            out += p4.w * vs[(j4 + 3) * KSTR + lane];
        }
        xout[((size_t)b * NT + i) * C_ + h * DH + lane] = out;
        __syncwarp();
    }
}

// ---------------------------------------------------------------------------
extern "C" void kernel_launch(void* const* d_in, const int* in_sizes, int n_in,
                              void* d_out, int out_size) {
    const float* skip   = (const float*)d_in[0];
    const float* x_up   = (const float*)d_in[1];
    const float* mask   = (const float*)d_in[2];
    const int*   rel    = (const int*)d_in[3];
    const float* table  = (const float*)d_in[4];
    const float* kv_w   = (const float*)d_in[5];
    const float* kv_b   = (const float*)d_in[6];
    const float* proj_w = (const float*)d_in[7];
    const float* proj_b = (const float*)d_in[8];
    float* out = (float*)d_out;

    float *kptr, *vptr, *xptr, *biasptr;
    cudaGetSymbolAddress((void**)&kptr, g_k);
    cudaGetSymbolAddress((void**)&vptr, g_v);
    cudaGetSymbolAddress((void**)&xptr, g_x);
    cudaGetSymbolAddress((void**)&biasptr, g_bias);

    // 1. bias gather
    bias_gather_kernel<<<(NT * NT + 255) / 256, 256>>>(rel, table, biasptr);

    // 2. kv projection GEMM (scatter into g_k / g_v)
    gemm_kernel<384, 0><<<dim3(M_ / 64, 384 / 64), 256>>>(skip, kv_w, kv_b, kptr, vptr);

    // 3. fused attention
    const int SMEM_BYTES = (2 * 344 * KSTR + 8 * 344) * (int)sizeof(float); // 110080
    cudaFuncSetAttribute(attn_kernel, cudaFuncAttributeMaxDynamicSharedMemorySize, SMEM_BYTES);
    attn_kernel<<<B_ * H_, 256, SMEM_BYTES>>>(x_up, kptr, vptr, biasptr, mask, xptr);

    // 4. output projection GEMM (+bias) straight to d_out
    gemm_kernel<192, 1><<<dim3(M_ / 64, 192 / 64), 256>>>(xptr, proj_w, proj_b, out, nullptr);
}

// round 2
// speedup vs baseline: 1.4095x; 1.4095x over previous
#include <cuda_runtime.h>

#define B_   256
#define H_   6
#define NT   343
#define NTP  344
#define DH   32
#define C_   192
#define NWIN 32
#define M_   (B_*NT)          // 87808
#define KS2  33               // k/v smem row stride (floats) -> conflict-free

// Scratch (static device allocations — allowed)
__device__ __align__(16) float g_k[(size_t)B_*H_*NT*DH];
__device__ __align__(16) float g_v[(size_t)B_*H_*NT*DH];
__device__ __align__(16) float g_x[(size_t)B_*NT*C_];
__device__ __align__(16) float g_bias[(size_t)H_*NT*NT];

// ---------------------------------------------------------------------------
// Kernel 1: gather relative-position bias  bias[h][i][j] = table[rel[i][j]][h]
// ---------------------------------------------------------------------------
__global__ void bias_gather_kernel(const int* __restrict__ rel,
                                   const float* __restrict__ table,
                                   float* __restrict__ bias) {
    int idx = blockIdx.x * 256 + threadIdx.x;
    if (idx < NT * NT) {
        int r = rel[idx];
        #pragma unroll
        for (int h = 0; h < H_; h++)
            bias[(size_t)h * (NT * NT) + idx] = table[r * H_ + h];
    }
}

// ---------------------------------------------------------------------------
// Tiled fp32 GEMM: (M x 192) @ (192 x NCOL) + bias, 64x64 tiles, 256 threads,
// 4x4 per thread. MODE 0: scatter kv -> g_k/g_v ; MODE 1: row-major out.
// ---------------------------------------------------------------------------
template <int NCOL, int MODE>
__global__ void gemm_kernel(const float* __restrict__ A,
                            const float* __restrict__ W,
                            const float* __restrict__ bias,
                            float* __restrict__ out0,
                            float* __restrict__ out1) {
    __shared__ float As[16][64];
    __shared__ float Bs[16][68];

    const int t  = threadIdx.x;          // 0..255
    const int M0 = blockIdx.x * 64;
    const int N0 = blockIdx.y * 64;
    const int ty = t >> 4, tx = t & 15;
    const int ar = t >> 2, ac = (t & 3) << 2;
    const int br = t >> 4, bc = (t & 15) << 2;

    float c[4][4] = {};

    for (int k0 = 0; k0 < 192; k0 += 16) {
        float4 a4 = *(const float4*)&A[(size_t)(M0 + ar) * 192 + k0 + ac];
        As[ac + 0][ar] = a4.x;
        As[ac + 1][ar] = a4.y;
        As[ac + 2][ar] = a4.z;
        As[ac + 3][ar] = a4.w;
        float4 b4 = *(const float4*)&W[(size_t)(k0 + br) * NCOL + N0 + bc];
        *(float4*)&Bs[br][bc] = b4;
        __syncthreads();
        #pragma unroll
        for (int kk = 0; kk < 16; kk++) {
            float4 av = *(const float4*)&As[kk][ty << 2];
            float4 bv = *(const float4*)&Bs[kk][tx << 2];
            float aa[4] = {av.x, av.y, av.z, av.w};
            float bb[4] = {bv.x, bv.y, bv.z, bv.w};
            #pragma unroll
            for (int i = 0; i < 4; i++)
                #pragma unroll
                for (int j = 0; j < 4; j++)
                    c[i][j] += aa[i] * bb[j];
        }
        __syncthreads();
    }

    #pragma unroll
    for (int i = 0; i < 4; i++) {
        int row = M0 + (ty << 2) + i;
        int b = row / NT, nn = row - b * NT;
        #pragma unroll
        for (int j = 0; j < 4; j++) {
            int col = N0 + (tx << 2) + j;
            float val = c[i][j] + bias[col];
            if (MODE == 0) {
                int p   = col / 192;
                int rem = col - p * 192;
                int h   = rem >> 5;
                int d   = rem & 31;
                float* dst = p ? out1 : out0;
                dst[((size_t)(b * H_ + h) * NT + nn) * DH + d] = val;
            } else {
                out0[(size_t)row * NCOL + col] = val;
            }
        }
    }
}

// ---------------------------------------------------------------------------
// Kernel 3: fused window attention, register-blocked.
// One CTA per (b,h), 512 threads = 16 warps, 1 CTA/SM (187KB smem).
// Each warp handles 4 query rows per iteration (6 iterations cover 384>=343).
// k,v in smem with stride 33 -> all lane-j / lane-d accesses conflict-free.
// Scores: acc[4][11] in registers; q staged per-warp, read as uniform LDS.
// ---------------------------------------------------------------------------
__global__ __launch_bounds__(512, 1)
void attn_kernel(const float* __restrict__ xup,
                 const float* __restrict__ gk,
                 const float* __restrict__ gv,
                 const float* __restrict__ bias,
                 const float* __restrict__ mask,
                 float* __restrict__ xout) {
    extern __shared__ float sm[];
    float* ks = sm;                         // 344 * 33
    float* vs = ks + NTP * KS2;             // 344 * 33
    float* qs = vs + NTP * KS2;             // 16 * 128
    float* ps = qs + 16 * 128;              // 16 * 4 * 344

    const int tid = threadIdx.x;
    const int bh  = blockIdx.x;             // b*6 + h
    const int b   = bh / H_;
    const int h   = bh - b * H_;
    const int w   = b & (NWIN - 1);

    // Stage k, v (global float4 reads, scalar smem writes at stride 33)
    const float4* kg = (const float4*)(gk + (size_t)bh * NT * DH);
    const float4* vg = (const float4*)(gv + (size_t)bh * NT * DH);
    for (int idx = tid; idx < NT * 8; idx += 512) {
        int j = idx >> 3, c = (idx & 7) << 2;
        float4 a4 = kg[idx];
        float* kd = ks + j * KS2 + c;
        kd[0] = a4.x; kd[1] = a4.y; kd[2] = a4.z; kd[3] = a4.w;
        float4 b4 = vg[idx];
        float* vd = vs + j * KS2 + c;
        vd[0] = b4.x; vd[1] = b4.y; vd[2] = b4.z; vd[3] = b4.w;
    }
    if (tid < KS2) {                         // zero pad row 343
        ks[343 * KS2 + tid] = 0.f;
        vs[343 * KS2 + tid] = 0.f;
    }
    __syncthreads();

    const int warp = tid >> 5, lane = tid & 31;
    const float scale = 0.17677669529663687f;     // 32^-0.5
    float* qw = qs + warp * 128;
    float* pw = ps + warp * 4 * NTP;
    const float* brow0 = bias + (size_t)h * NT * NT;
    const float* mrow0 = mask + (size_t)w * NT * NT;

    for (int it = 0; it < 6; it++) {
        const int row0 = it * 64 + warp * 4;

        // stage 4 scaled q rows for this warp
        #pragma unroll
        for (int rr = 0; rr < 4; rr++) {
            int row = min(row0 + rr, NT - 1);
            qw[rr * 32 + lane] =
                xup[((size_t)b * NT + row) * C_ + h * DH + lane] * scale;
        }
        __syncwarp();

        // ---- scores: acc[r][tt] for j = 32*tt + lane ----
        float acc[4][11];
        #pragma unroll
        for (int r = 0; r < 4; r++)
            #pragma unroll
            for (int tt = 0; tt < 11; tt++) acc[r][tt] = 0.f;

        #pragma unroll
        for (int dc = 0; dc < 32; dc += 8) {
            float qr[4][8];
            #pragma unroll
            for (int r = 0; r < 4; r++)
                #pragma unroll
                for (int dd = 0; dd < 8; dd++)
                    qr[r][dd] = qw[r * 32 + dc + dd];   // uniform broadcast
            #pragma unroll
            for (int tt = 0; tt < 11; tt++) {
                int j  = tt * 32 + lane;
                int jc = min(j, NT);                    // row 343 is zero-pad
                const float* kp = ks + jc * KS2 + dc;
                #pragma unroll
                for (int dd = 0; dd < 8; dd++) {
                    float kv = kp[dd];
                    #pragma unroll
                    for (int r = 0; r < 4; r++)
                        acc[r][tt] += qr[r][dd] * kv;
                }
            }
        }

        // ---- epilogue + softmax per row, write p ----
        #pragma unroll
        for (int r = 0; r < 4; r++) {
            int row = min(row0 + r, NT - 1);
            const float* br = brow0 + (size_t)row * NT;
            const float* mr = mrow0 + (size_t)row * NT;
            float sreg[11];
            float mx = -1e30f;
            #pragma unroll
            for (int tt = 0; tt < 11; tt++) {
                int j = tt * 32 + lane;
                float s = -1e30f;
                if (j < NT) s = acc[r][tt] + br[j] + mr[j];
                sreg[tt] = s;
                mx = fmaxf(mx, s);
            }
            #pragma unroll
            for (int o = 16; o > 0; o >>= 1)
                mx = fmaxf(mx, __shfl_xor_sync(0xffffffffu, mx, o));
            float sum = 0.f;
            #pragma unroll
            for (int tt = 0; tt < 11; tt++) {
                float e = __expf(sreg[tt] - mx);
                sreg[tt] = e;
                sum += e;
            }
            #pragma unroll
            for (int o = 16; o > 0; o >>= 1)
                sum += __shfl_xor_sync(0xffffffffu, sum, o);
            float inv = 1.f / sum;
            #pragma unroll
            for (int tt = 0; tt < 11; tt++) {
                int j = tt * 32 + lane;
                if (j < NT) pw[r * NTP + j] = sreg[tt] * inv;
            }
            if (lane == 0) pw[r * NTP + NT] = 0.f;
        }
        __syncwarp();

        // ---- AV: lane owns d = lane, 4 rows at once ----
        float o0 = 0.f, o1 = 0.f, o2 = 0.f, o3 = 0.f;
        #pragma unroll 2
        for (int j4 = 0; j4 < NTP; j4 += 4) {
            float vv0 = vs[(j4 + 0) * KS2 + lane];
            float vv1 = vs[(j4 + 1) * KS2 + lane];
            float vv2 = vs[(j4 + 2) * KS2 + lane];
            float vv3 = vs[(j4 + 3) * KS2 + lane];
            float4 p0 = *(const float4*)&pw[0 * NTP + j4];
            float4 p1 = *(const float4*)&pw[1 * NTP + j4];
            float4 p2 = *(const float4*)&pw[2 * NTP + j4];
            float4 p3 = *(const float4*)&pw[3 * NTP + j4];
            o0 += p0.x * vv0 + p0.y * vv1 + p0.z * vv2 + p0.w * vv3;
            o1 += p1.x * vv0 + p1.y * vv1 + p1.z * vv2 + p1.w * vv3;
            o2 += p2.x * vv0 + p2.y * vv1 + p2.z * vv2 + p2.w * vv3;
            o3 += p3.x * vv0 + p3.y * vv1 + p3.z * vv2 + p3.w * vv3;
        }

        float ov[4] = {o0, o1, o2, o3};
        #pragma unroll
        for (int r = 0; r < 4; r++) {
            int row = row0 + r;
            if (row < NT)
                xout[((size_t)b * NT + row) * C_ + h * DH + lane] = ov[r];
        }
        __syncwarp();
    }
}

// ---------------------------------------------------------------------------
extern "C" void kernel_launch(void* const* d_in, const int* in_sizes, int n_in,
                              void* d_out, int out_size) {
    const float* skip   = (const float*)d_in[0];
    const float* x_up   = (const float*)d_in[1];
    const float* mask   = (const float*)d_in[2];
    const int*   rel    = (const int*)d_in[3];
    const float* table  = (const float*)d_in[4];
    const float* kv_w   = (const float*)d_in[5];
    const float* kv_b   = (const float*)d_in[6];
    const float* proj_w = (const float*)d_in[7];
    const float* proj_b = (const float*)d_in[8];
    float* out = (float*)d_out;

    float *kptr, *vptr, *xptr, *biasptr;
    cudaGetSymbolAddress((void**)&kptr, g_k);
    cudaGetSymbolAddress((void**)&vptr, g_v);
    cudaGetSymbolAddress((void**)&xptr, g_x);
    cudaGetSymbolAddress((void**)&biasptr, g_bias);

    // 1. bias gather
    bias_gather_kernel<<<(NT * NT + 255) / 256, 256>>>(rel, table, biasptr);

    // 2. kv projection GEMM (scatter into g_k / g_v)
    gemm_kernel<384, 0><<<dim3(M_ / 64, 384 / 64), 256>>>(skip, kv_w, kv_b, kptr, vptr);

    // 3. fused attention
    const int SMEM_BYTES = (2 * NTP * KS2 + 16 * 128 + 16 * 4 * NTP) * (int)sizeof(float);
    cudaFuncSetAttribute(attn_kernel, cudaFuncAttributeMaxDynamicSharedMemorySize, SMEM_BYTES);
    attn_kernel<<<B_ * H_, 512, SMEM_BYTES>>>(x_up, kptr, vptr, biasptr, mask, xptr);

    // 4. output projection GEMM (+bias) straight to d_out
    gemm_kernel<192, 1><<<dim3(M_ / 64, 192 / 64), 256>>>(xptr, proj_w, proj_b, out, nullptr);
}